// round 12
// baseline (speedup 1.0000x reference)
#include <cuda_runtime.h>
#include <cuda_bf16.h>
#include <math.h>
#include <stdint.h>

#define TT 1024
#define DD 512
#define EE 10
#define HH 2048
#define CEC 32
#define LIN 928
#define NTOK 4096
#define NPAIR 8192

#define BM 128
#define BN 128
#define BK 32           // bf16 k per stage

// A tile: 128 rows x 32 bf16, 80B pitch (conflict-free ldmatrix) = 10240B
// B tile: 32 k-rows x 128 bf16, 256B pitch, chunk-XOR swizzle = 8192B
#define A_TILE 10240
#define B_TILE 8192
#define OFF_AH 0
#define OFF_AL A_TILE
#define OFF_BH (2 * A_TILE)
#define OFF_BL (2 * A_TILE + B_TILE)
#define STAGE  (2 * A_TILE + 2 * B_TILE)   // 36864
#define NSTAGE 3
#define SMEM_DYN (NSTAGE * STAGE)          // 110592 (2 CTAs = 216KB <= 228KB)

// Scratch (static device arrays — no allocation allowed)
__device__ __align__(16) __nv_bfloat16 g_hid_h[(size_t)NPAIR * HH];   // 32 MB
__device__ __align__(16) __nv_bfloat16 g_hid_l[(size_t)NPAIR * HH];   // 32 MB
__device__ __align__(16) __nv_bfloat16 g_xh[(size_t)NTOK * DD];
__device__ __align__(16) __nv_bfloat16 g_xl[(size_t)NTOK * DD];
__device__ __align__(16) __nv_bfloat16 g_w1h[(size_t)EE * DD * HH];
__device__ __align__(16) __nv_bfloat16 g_w1l[(size_t)EE * DD * HH];
__device__ __align__(16) __nv_bfloat16 g_w2h[(size_t)EE * HH * DD];
__device__ __align__(16) __nv_bfloat16 g_w2l[(size_t)EE * HH * DD];
__device__ int   g_count[EE];
__device__ int   g_entry[EE * NTOK];          // packed: token*2 + slot
__device__ float g_wt[EE * NTOK];

__global__ void zero_counts_kernel() {
    if (threadIdx.x < EE) g_count[threadIdx.x] = 0;
}

// ---------------------------------------------------------------------------
// helpers
// ---------------------------------------------------------------------------
__device__ __forceinline__ uint32_t sm_u32(const void* p) {
    return (uint32_t)__cvta_generic_to_shared(p);
}
__device__ __forceinline__ void bsplit(float v, uint32_t& h, uint32_t& l) {
    __nv_bfloat16 bh = __float2bfloat16_rn(v);
    h = (uint32_t)__bfloat16_as_ushort(bh);
    l = (uint32_t)__bfloat16_as_ushort(__float2bfloat16_rn(v - __bfloat162float(bh)));
}

#define MMA_BF16(d, a0, a1, a2, a3, b0, b1)                                   \
    asm volatile(                                                             \
        "mma.sync.aligned.m16n8k16.row.col.f32.bf16.bf16.f32 "                \
        "{%0,%1,%2,%3}, {%4,%5,%6,%7}, {%8,%9}, {%0,%1,%2,%3};"               \
        : "+f"((d)[0]), "+f"((d)[1]), "+f"((d)[2]), "+f"((d)[3])              \
        : "r"(a0), "r"(a1), "r"(a2), "r"(a3), "r"(b0), "r"(b1))

#define LDSM_X4(r0, r1, r2, r3, addr)                                         \
    asm volatile("ldmatrix.sync.aligned.m8n8.x4.shared.b16 {%0,%1,%2,%3}, [%4];" \
        : "=r"(r0), "=r"(r1), "=r"(r2), "=r"(r3) : "r"(addr))

#define LDSM_X4T(r0, r1, r2, r3, addr)                                        \
    asm volatile("ldmatrix.sync.aligned.m8n8.x4.trans.shared.b16 {%0,%1,%2,%3}, [%4];" \
        : "=r"(r0), "=r"(r1), "=r"(r2), "=r"(r3) : "r"(addr))

// cp.async: A uses .ca (L1, co-resident CTAs share m-tile), B uses .cg (L2 only)
#define CPA(dst, src, sz)                                                     \
    asm volatile("cp.async.ca.shared.global [%0], [%1], 16, %2;"              \
        :: "r"(dst), "l"(src), "r"(sz) : "memory")
#define CPB(dst, src)                                                         \
    asm volatile("cp.async.cg.shared.global [%0], [%1], 16;"                  \
        :: "r"(dst), "l"(src) : "memory")
#define CP_COMMIT() asm volatile("cp.async.commit_group;" ::: "memory")
#define CP_WAIT0()  asm volatile("cp.async.wait_group 0;" ::: "memory")
#define CP_WAIT1()  asm volatile("cp.async.wait_group 1;" ::: "memory")

// ---------------------------------------------------------------------------
// Pre-split: fp32 -> bf16 hi/lo pair, vectorized float4.
// ---------------------------------------------------------------------------
__global__ __launch_bounds__(256)
void presplit_kernel(const float* __restrict__ src,
                     __nv_bfloat16* __restrict__ h,
                     __nv_bfloat16* __restrict__ l, int n4)
{
    int i = blockIdx.x * 256 + threadIdx.x;
    if (i >= n4) return;
    float4 v = ((const float4*)src)[i];
    uint32_t hh[4], ll[4];
    bsplit(v.x, hh[0], ll[0]); bsplit(v.y, hh[1], ll[1]);
    bsplit(v.z, hh[2], ll[2]); bsplit(v.w, hh[3], ll[3]);
    ((uint2*)h)[i] = make_uint2(hh[0] | (hh[1] << 16), hh[2] | (hh[3] << 16));
    ((uint2*)l)[i] = make_uint2(ll[0] | (ll[1] << 16), ll[2] | (ll[3] << 16));
}

// ---------------------------------------------------------------------------
// Router: 32 tokens per block, weights staged in smem.
// ---------------------------------------------------------------------------
#define RTOK 32
#define RCH 116   // 928 / 8 chunks

__global__ __launch_bounds__(256)
void router_kernel(const float* __restrict__ x,
                   const float* __restrict__ dt,
                   const float* __restrict__ dd,
                   const float* __restrict__ dr,
                   const float* __restrict__ de,
                   const float* __restrict__ cemb,
                   const float* __restrict__ Wg,
                   const float* __restrict__ bg,
                   const float* __restrict__ Wn,
                   const float* __restrict__ bn,
                   const float* __restrict__ noise,
                   const int*   __restrict__ city,
                   float* __restrict__ gate1)
{
    __shared__ float Wsh[2 * EE][RCH];
    __shared__ float hsh[RTOK][RCH];
    __shared__ float lg[RTOK][2 * EE];

    const int tid = threadIdx.x;          // 256
    const int tb = blockIdx.x * RTOK;
    const int t = tid >> 3;               // token slot 0..31
    const int s = tid & 7;                // 0..7

    float acc0 = 0.f, acc1 = 0.f, acc2 = 0.f;

    for (int c = 0; c < 8; c++) {
        const int k0 = c * RCH;
        for (int i = tid; i < 2 * EE * RCH; i += 256) {
            int j = i / RCH, k = i % RCH;
            Wsh[j][k] = (j < EE) ? Wg[j * LIN + k0 + k] : Wn[(j - EE) * LIN + k0 + k];
        }
        for (int i = tid; i < RTOK * RCH; i += 256) {
            int tt = i / RCH, kk = i % RCH;
            int k = k0 + kk;
            int n = tb + tt;
            float v;
            if (k < DD)        v = x[n * DD + k];
            else if (k < 544)  v = cemb[city[n / TT] * CEC + (k - DD)];
            else if (k < 672)  v = dt[n * 128 + (k - 544)];
            else if (k < 800)  v = dd[n * 128 + (k - 672)];
            else if (k < 864)  v = dr[n * 64 + (k - 800)];
            else               v = de[n * 64 + (k - 864)];
            hsh[tt][kk] = v;
        }
        __syncthreads();
        for (int k = 0; k < RCH; k++) {
            float a = hsh[t][k];
            acc0 += a * Wsh[s][k];
            acc1 += a * Wsh[s + 8][k];
            if (s < 4) acc2 += a * Wsh[s + 16][k];
        }
        __syncthreads();
    }
    lg[t][s] = acc0;
    lg[t][s + 8] = acc1;
    if (s < 4) lg[t][s + 16] = acc2;
    __syncthreads();

    if (s == 0) {
        const int n = tb + t;
        float logits[EE], noisy[EE], ex[EE];
        float mx = -1e30f;
        for (int e = 0; e < EE; e++) { logits[e] = lg[t][e] + bg[e]; mx = fmaxf(mx, logits[e]); }
        float ssum = 0.f;
        for (int e = 0; e < EE; e++) { ex[e] = expf(logits[e] - mx); ssum += ex[e]; }
        const float rinv = 1.f / ssum;
        for (int e = 0; e < EE; e++) gate1[n * EE + e] = ex[e] * rinv;

        for (int e = 0; e < EE; e++) {
            const float z  = lg[t][EE + e] + bn[e];
            const float sp = fmaxf(z, 0.f) + log1pf(expf(-fabsf(z)));  // stable softplus
            noisy[e] = logits[e] + noise[n * EE + e] * sp;
        }
        int i0 = 0;
        for (int e = 1; e < EE; e++) if (noisy[e] > noisy[i0]) i0 = e;
        int i1 = (i0 == 0) ? 1 : 0;
        for (int e = 0; e < EE; e++) if (e != i0 && noisy[e] > noisy[i1]) i1 = e;

        const float m  = fmaxf(noisy[i0], noisy[i1]);
        const float s0 = expf(noisy[i0] - m), s1 = expf(noisy[i1] - m);
        const float inv = 1.f / (s0 + s1);

        int p0 = atomicAdd(&g_count[i0], 1);
        g_entry[i0 * NTOK + p0] = 2 * n;
        g_wt[i0 * NTOK + p0]    = s0 * inv;
        int p1 = atomicAdd(&g_count[i1], 1);
        g_entry[i1 * NTOK + p1] = 2 * n + 1;
        g_wt[i1 * NTOK + p1]    = s1 * inv;
    }
}

// ---------------------------------------------------------------------------
// Gathered expert GEMM: mma.sync m16n8k16 bf16, 3xBF16 split, fp32 accum.
// All operands pre-split to bf16 hi/lo in gmem; fills are pure cp.async.
//   IS_FFN2 == false: hid(hi,lo)[pair] = split(gelu(x[tok] @ W1[e] + b1[e]))
//   IS_FFN2 == true : out[tok] += w * (hid[pair] @ W2[e] + b2[e])
// Block 128x128, BK=32 (2 k-steps of 16), 8 warps 4x2, warp tile 32x64.
// 2 CTAs/SM; 3-stage cp.async pipeline (fills get 2 compute-stages of slack);
// MMA issue interleaved across 4 independent chains (dep distance 4).
// ---------------------------------------------------------------------------
template<int KTOT, int LDW, bool IS_FFN2>
__global__ __launch_bounds__(256, 2)
void moe_mma_kernel(const float* __restrict__ bias,
                    float* __restrict__ outp)
{
    constexpr int NT = KTOT / BK;
    const int e  = blockIdx.z;
    const int m0 = blockIdx.y * BM;
    const int n0 = blockIdx.x * BN;
    const int L  = g_count[e];
    if (m0 >= L) return;

    extern __shared__ char smem[];
    __shared__ int   toks[BM];
    __shared__ float wts[BM];

    const int tid  = threadIdx.x;
    const int wid  = tid >> 5;
    const int lane = tid & 31;

    if (tid < BM) {
        int i = m0 + tid;
        toks[tid] = (i < L) ? g_entry[e * NTOK + i] : -1;
        wts[tid]  = (IS_FFN2 && i < L) ? g_wt[e * NTOK + i] : 0.f;
    }
    __syncthreads();

    const char* Ah = IS_FFN2 ? (const char*)g_hid_h : (const char*)g_xh;
    const char* Al = IS_FFN2 ? (const char*)g_hid_l : (const char*)g_xl;
    const char* Wh = IS_FFN2 ? (const char*)g_w2h : (const char*)g_w1h;
    const char* Wl = IS_FFN2 ? (const char*)g_w2l : (const char*)g_w1l;

    // ---- cp.async fills ----
    auto fill_stage = [&](int buf, int k0) {
        char* st = smem + buf * STAGE;
        // A: 128 rows x 4 chunks of 16B, hi+lo; 2 passes
        #pragma unroll
        for (int p = 0; p < 2; p++) {
            const int idx = p * 256 + tid;
            const int r = idx >> 2, c = idx & 3;
            const int ent = toks[r];
            const int row = ent >= 0 ? (IS_FFN2 ? ent : (ent >> 1)) : 0;
            const uint32_t sz = ent >= 0 ? 16u : 0u;
            const size_t so = ((size_t)row * KTOT + k0 + c * 8) * 2;
            CPA(sm_u32(st + OFF_AH + r * 80 + c * 16), Ah + so, sz);
            CPA(sm_u32(st + OFF_AL + r * 80 + c * 16), Al + so, sz);
        }
        // B: 32 k-rows x 16 chunks of 16B, hi+lo; 2 passes
        const size_t wbase = ((size_t)e * KTOT + k0) * LDW + n0;
        #pragma unroll
        for (int p = 0; p < 2; p++) {
            const int idx = p * 256 + tid;
            const int k = idx >> 4, c = idx & 15;
            const size_t so = (wbase + (size_t)k * LDW + c * 8) * 2;
            const int doff = k * 256 + ((c ^ (k & 7)) * 16);
            CPB(sm_u32(st + OFF_BH + doff), Wh + so);
            CPB(sm_u32(st + OFF_BL + doff), Wl + so);
        }
    };

    // ---- accumulators ----
    const int wm = wid >> 1, wn = wid & 1;
    float acc[2][8][4];
    #pragma unroll
    for (int mt = 0; mt < 2; mt++)
        #pragma unroll
        for (int nn = 0; nn < 8; nn++)
            #pragma unroll
            for (int i = 0; i < 4; i++) acc[mt][nn][i] = 0.f;

    auto compute_stage = [&](int buf) {
        char* st = smem + buf * STAGE;
        const uint32_t ah = sm_u32(st + OFF_AH);
        const uint32_t al = sm_u32(st + OFF_AL);
        const uint32_t bh = sm_u32(st + OFF_BH);
        const uint32_t bl = sm_u32(st + OFF_BL);
        #pragma unroll
        for (int ks = 0; ks < 2; ks++) {
            // A frags: rows lane&15, k-half lane>>4
            uint32_t a_h[2][4], a_l[2][4];
            #pragma unroll
            for (int mt = 0; mt < 2; mt++) {
                const uint32_t ao = (wm * 32 + mt * 16 + (lane & 15)) * 80
                                  + ks * 32 + (lane >> 4) * 16;
                LDSM_X4(a_h[mt][0], a_h[mt][1], a_h[mt][2], a_h[mt][3], ah + ao);
                LDSM_X4(a_l[mt][0], a_l[mt][1], a_l[mt][2], a_l[mt][3], al + ao);
            }
            // B frags per-bt; MMAs interleaved across 4 chains (2 mt x d0/d1)
            #pragma unroll
            for (int bt = 0; bt < 4; bt++) {
                uint32_t bfh[4], bfl[4];
                const int k = ks * 16 + (lane & 15);
                const int c = ((wn * 64 + bt * 16) >> 3) + (lane >> 4);
                const uint32_t bo = k * 256 + ((c ^ (lane & 7)) * 16);
                LDSM_X4T(bfh[0], bfh[1], bfh[2], bfh[3], bh + bo);
                LDSM_X4T(bfl[0], bfl[1], bfl[2], bfl[3], bl + bo);
                // term 1: Ah*Bh  (4 independent MMAs)
                #pragma unroll
                for (int mt = 0; mt < 2; mt++) {
                    MMA_BF16(acc[mt][2 * bt],     a_h[mt][0], a_h[mt][1], a_h[mt][2], a_h[mt][3], bfh[0], bfh[1]);
                    MMA_BF16(acc[mt][2 * bt + 1], a_h[mt][0], a_h[mt][1], a_h[mt][2], a_h[mt][3], bfh[2], bfh[3]);
                }
                // term 2: Ah*Bl
                #pragma unroll
                for (int mt = 0; mt < 2; mt++) {
                    MMA_BF16(acc[mt][2 * bt],     a_h[mt][0], a_h[mt][1], a_h[mt][2], a_h[mt][3], bfl[0], bfl[1]);
                    MMA_BF16(acc[mt][2 * bt + 1], a_h[mt][0], a_h[mt][1], a_h[mt][2], a_h[mt][3], bfl[2], bfl[3]);
                }
                // term 3: Al*Bh
                #pragma unroll
                for (int mt = 0; mt < 2; mt++) {
                    MMA_BF16(acc[mt][2 * bt],     a_l[mt][0], a_l[mt][1], a_l[mt][2], a_l[mt][3], bfh[0], bfh[1]);
                    MMA_BF16(acc[mt][2 * bt + 1], a_l[mt][0], a_l[mt][1], a_l[mt][2], a_l[mt][3], bfh[2], bfh[3]);
                }
            }
        }
    };

    // ---- mainloop: 3-stage pipeline ----
    fill_stage(0, 0);
    CP_COMMIT();
    if (NT > 1) { fill_stage(1, BK); CP_COMMIT(); }
    int buf = 0, nxt = (NT > 1) ? 2 : 1;
    for (int t = 0; t < NT; t++) {
        if (t + 1 < NT) CP_WAIT1(); else CP_WAIT0();
        __syncthreads();
        if (t + 2 < NT) {
            fill_stage(nxt, (t + 2) * BK);
            CP_COMMIT();
            if (++nxt == NSTAGE) nxt = 0;
        }
        compute_stage(buf);
        if (++buf == NSTAGE) buf = 0;
    }

    // ---- epilogue ----
    const int g  = lane >> 2;
    const int kq = lane & 3;
    const float* be = bias + e * LDW;
    #pragma unroll
    for (int mt = 0; mt < 2; mt++) {
        const int lr0  = wm * 32 + mt * 16 + g;
        const int ent0 = toks[lr0];
        const int ent1 = toks[lr0 + 8];
        #pragma unroll
        for (int nn = 0; nn < 8; nn++) {
            const int c = n0 + wn * 64 + nn * 8 + 2 * kq;
            const float bb0 = be[c], bb1 = be[c + 1];
            if (!IS_FFN2) {
                if (ent0 >= 0) {
                    float v0 = acc[mt][nn][0] + bb0;
                    float v1 = acc[mt][nn][1] + bb1;
                    v0 = 0.5f * v0 * (1.f + erff(v0 * 0.70710678118654752f));
                    v1 = 0.5f * v1 * (1.f + erff(v1 * 0.70710678118654752f));
                    uint32_t h0, l0, h1, l1;
                    bsplit(v0, h0, l0); bsplit(v1, h1, l1);
                    const size_t o = ((size_t)ent0 * HH + c) * 2;
                    *(uint32_t*)((char*)g_hid_h + o) = h0 | (h1 << 16);
                    *(uint32_t*)((char*)g_hid_l + o) = l0 | (l1 << 16);
                }
                if (ent1 >= 0) {
                    float v0 = acc[mt][nn][2] + bb0;
                    float v1 = acc[mt][nn][3] + bb1;
                    v0 = 0.5f * v0 * (1.f + erff(v0 * 0.70710678118654752f));
                    v1 = 0.5f * v1 * (1.f + erff(v1 * 0.70710678118654752f));
                    uint32_t h0, l0, h1, l1;
                    bsplit(v0, h0, l0); bsplit(v1, h1, l1);
                    const size_t o = ((size_t)ent1 * HH + c) * 2;
                    *(uint32_t*)((char*)g_hid_h + o) = h0 | (h1 << 16);
                    *(uint32_t*)((char*)g_hid_l + o) = l0 | (l1 << 16);
                }
            } else {
                if (ent0 >= 0) {
                    const float w = wts[lr0];
                    float* o = outp + (size_t)(ent0 >> 1) * DD + c;
                    atomicAdd(o,     w * (acc[mt][nn][0] + bb0));
                    atomicAdd(o + 1, w * (acc[mt][nn][1] + bb1));
                }
                if (ent1 >= 0) {
                    const float w = wts[lr0 + 8];
                    float* o = outp + (size_t)(ent1 >> 1) * DD + c;
                    atomicAdd(o,     w * (acc[mt][nn][2] + bb0));
                    atomicAdd(o + 1, w * (acc[mt][nn][3] + bb1));
                }
            }
        }
    }
}

// ---------------------------------------------------------------------------
extern "C" void kernel_launch(void* const* d_in, const int* in_sizes, int n_in,
                              void* d_out, int out_size)
{
    const float* x    = (const float*)d_in[0];
    const float* dt   = (const float*)d_in[1];
    const float* dd   = (const float*)d_in[2];
    const float* dr   = (const float*)d_in[3];
    const float* de   = (const float*)d_in[4];
    const float* cemb = (const float*)d_in[5];
    const float* Wg   = (const float*)d_in[6];
    const float* bg   = (const float*)d_in[7];
    const float* Wn   = (const float*)d_in[8];
    const float* bn   = (const float*)d_in[9];
    const float* W1   = (const float*)d_in[10];
    const float* b1   = (const float*)d_in[11];
    const float* W2   = (const float*)d_in[12];
    const float* b2   = (const float*)d_in[13];
    const float* noise= (const float*)d_in[14];
    const int*   city = (const int*)d_in[15];

    float* out   = (float*)d_out;                       // (4096, 512)
    float* gate1 = (float*)d_out + (size_t)NTOK * DD;   // (4096, 10)

    cudaFuncSetAttribute((const void*)moe_mma_kernel<DD, HH, false>,
                         cudaFuncAttributeMaxDynamicSharedMemorySize, SMEM_DYN);
    cudaFuncSetAttribute((const void*)moe_mma_kernel<HH, DD, true>,
                         cudaFuncAttributeMaxDynamicSharedMemorySize, SMEM_DYN);

    cudaMemsetAsync(d_out, 0, (size_t)NTOK * DD * sizeof(float));
    zero_counts_kernel<<<1, 32>>>();

    // pre-split operands to bf16 hi/lo (once)
    {
        __nv_bfloat16 *xh, *xl, *w1h, *w1l, *w2h, *w2l;
        cudaGetSymbolAddress((void**)&xh,  g_xh);
        cudaGetSymbolAddress((void**)&xl,  g_xl);
        cudaGetSymbolAddress((void**)&w1h, g_w1h);
        cudaGetSymbolAddress((void**)&w1l, g_w1l);
        cudaGetSymbolAddress((void**)&w2h, g_w2h);
        cudaGetSymbolAddress((void**)&w2l, g_w2l);
        const int nx = NTOK * DD / 4;
        const int nw = EE * DD * HH / 4;
        presplit_kernel<<<(nx + 255) / 256, 256>>>(x,  xh,  xl,  nx);
        presplit_kernel<<<(nw + 255) / 256, 256>>>(W1, w1h, w1l, nw);
        presplit_kernel<<<(nw + 255) / 256, 256>>>(W2, w2h, w2l, nw);
    }

    router_kernel<<<NTOK / RTOK, 256>>>(x, dt, dd, dr, de, cemb, Wg, bg, Wn, bn,
                                        noise, city, gate1);

    dim3 grid1(HH / BN, NTOK / BM, EE);   // (16, 32, 10)
    moe_mma_kernel<DD, HH, false><<<grid1, 256, SMEM_DYN>>>(b1, nullptr);

    dim3 grid2(DD / BN, NTOK / BM, EE);   // (4, 32, 10)
    moe_mma_kernel<HH, DD, true><<<grid2, 256, SMEM_DYN>>>(b2, out);
}

// round 13
// speedup vs baseline: 1.0001x; 1.0001x over previous
#include <cuda_runtime.h>
#include <cuda_bf16.h>
#include <math.h>
#include <stdint.h>

#define TT 1024
#define DD 512
#define EE 10
#define HH 2048
#define CEC 32
#define LIN 928
#define NTOK 4096
#define NPAIR 8192

#define BM 128
#define BN 128
#define BK 32           // bf16 k per stage

// A tile: 128 rows x 32 bf16, 80B pitch (conflict-free ldmatrix) = 10240B
// B tile: 32 k-rows x 128 bf16, 256B pitch, chunk-XOR swizzle = 8192B
#define A_TILE 10240
#define B_TILE 8192
#define OFF_AH 0
#define OFF_AL A_TILE
#define OFF_BH (2 * A_TILE)
#define OFF_BL (2 * A_TILE + B_TILE)
#define STAGE  (2 * A_TILE + 2 * B_TILE)   // 36864
#define NSTAGE 3
#define SMEM_DYN (NSTAGE * STAGE)          // 110592 (2 CTAs = 216KB <= 228KB)

// Scratch (static device arrays — no allocation allowed)
__device__ __align__(16) __nv_bfloat16 g_hid_h[(size_t)NPAIR * HH];   // 32 MB
__device__ __align__(16) __nv_bfloat16 g_hid_l[(size_t)NPAIR * HH];   // 32 MB
__device__ __align__(16) __nv_bfloat16 g_xh[(size_t)NTOK * DD];
__device__ __align__(16) __nv_bfloat16 g_xl[(size_t)NTOK * DD];
__device__ __align__(16) __nv_bfloat16 g_w1h[(size_t)EE * DD * HH];
__device__ __align__(16) __nv_bfloat16 g_w1l[(size_t)EE * DD * HH];
__device__ __align__(16) __nv_bfloat16 g_w2h[(size_t)EE * HH * DD];
__device__ __align__(16) __nv_bfloat16 g_w2l[(size_t)EE * HH * DD];
__device__ int   g_count[EE];
__device__ int   g_entry[EE * NTOK];          // packed: token*2 + slot
__device__ float g_wt[EE * NTOK];

__global__ void zero_counts_kernel() {
    if (threadIdx.x < EE) g_count[threadIdx.x] = 0;
}

// ---------------------------------------------------------------------------
// helpers
// ---------------------------------------------------------------------------
__device__ __forceinline__ uint32_t sm_u32(const void* p) {
    return (uint32_t)__cvta_generic_to_shared(p);
}
__device__ __forceinline__ void bsplit(float v, uint32_t& h, uint32_t& l) {
    __nv_bfloat16 bh = __float2bfloat16_rn(v);
    h = (uint32_t)__bfloat16_as_ushort(bh);
    l = (uint32_t)__bfloat16_as_ushort(__float2bfloat16_rn(v - __bfloat162float(bh)));
}

#define MMA_BF16(d, a0, a1, a2, a3, b0, b1)                                   \
    asm volatile(                                                             \
        "mma.sync.aligned.m16n8k16.row.col.f32.bf16.bf16.f32 "                \
        "{%0,%1,%2,%3}, {%4,%5,%6,%7}, {%8,%9}, {%0,%1,%2,%3};"               \
        : "+f"((d)[0]), "+f"((d)[1]), "+f"((d)[2]), "+f"((d)[3])              \
        : "r"(a0), "r"(a1), "r"(a2), "r"(a3), "r"(b0), "r"(b1))

#define LDSM_X4(r0, r1, r2, r3, addr)                                         \
    asm volatile("ldmatrix.sync.aligned.m8n8.x4.shared.b16 {%0,%1,%2,%3}, [%4];" \
        : "=r"(r0), "=r"(r1), "=r"(r2), "=r"(r3) : "r"(addr))

#define LDSM_X4T(r0, r1, r2, r3, addr)                                        \
    asm volatile("ldmatrix.sync.aligned.m8n8.x4.trans.shared.b16 {%0,%1,%2,%3}, [%4];" \
        : "=r"(r0), "=r"(r1), "=r"(r2), "=r"(r3) : "r"(addr))

// cp.async: A uses .ca (L1, co-resident CTAs share m-tile), B uses .cg (L2 only)
#define CPA(dst, src, sz)                                                     \
    asm volatile("cp.async.ca.shared.global [%0], [%1], 16, %2;"              \
        :: "r"(dst), "l"(src), "r"(sz) : "memory")
#define CPB(dst, src)                                                         \
    asm volatile("cp.async.cg.shared.global [%0], [%1], 16;"                  \
        :: "r"(dst), "l"(src) : "memory")
#define CP_COMMIT() asm volatile("cp.async.commit_group;" ::: "memory")
#define CP_WAIT0()  asm volatile("cp.async.wait_group 0;" ::: "memory")
#define CP_WAIT1()  asm volatile("cp.async.wait_group 1;" ::: "memory")

// ---------------------------------------------------------------------------
// Pre-split: fp32 -> bf16 hi/lo pair, vectorized float4.
// ---------------------------------------------------------------------------
__global__ __launch_bounds__(256)
void presplit_kernel(const float* __restrict__ src,
                     __nv_bfloat16* __restrict__ h,
                     __nv_bfloat16* __restrict__ l, int n4)
{
    int i = blockIdx.x * 256 + threadIdx.x;
    if (i >= n4) return;
    float4 v = ((const float4*)src)[i];
    uint32_t hh[4], ll[4];
    bsplit(v.x, hh[0], ll[0]); bsplit(v.y, hh[1], ll[1]);
    bsplit(v.z, hh[2], ll[2]); bsplit(v.w, hh[3], ll[3]);
    ((uint2*)h)[i] = make_uint2(hh[0] | (hh[1] << 16), hh[2] | (hh[3] << 16));
    ((uint2*)l)[i] = make_uint2(ll[0] | (ll[1] << 16), ll[2] | (ll[3] << 16));
}

// ---------------------------------------------------------------------------
// Router: 32 tokens per block, weights staged in smem.
// ---------------------------------------------------------------------------
#define RTOK 32
#define RCH 116   // 928 / 8 chunks

__global__ __launch_bounds__(256)
void router_kernel(const float* __restrict__ x,
                   const float* __restrict__ dt,
                   const float* __restrict__ dd,
                   const float* __restrict__ dr,
                   const float* __restrict__ de,
                   const float* __restrict__ cemb,
                   const float* __restrict__ Wg,
                   const float* __restrict__ bg,
                   const float* __restrict__ Wn,
                   const float* __restrict__ bn,
                   const float* __restrict__ noise,
                   const int*   __restrict__ city,
                   float* __restrict__ gate1)
{
    __shared__ float Wsh[2 * EE][RCH];
    __shared__ float hsh[RTOK][RCH];
    __shared__ float lg[RTOK][2 * EE];

    const int tid = threadIdx.x;          // 256
    const int tb = blockIdx.x * RTOK;
    const int t = tid >> 3;               // token slot 0..31
    const int s = tid & 7;                // 0..7

    float acc0 = 0.f, acc1 = 0.f, acc2 = 0.f;

    for (int c = 0; c < 8; c++) {
        const int k0 = c * RCH;
        for (int i = tid; i < 2 * EE * RCH; i += 256) {
            int j = i / RCH, k = i % RCH;
            Wsh[j][k] = (j < EE) ? Wg[j * LIN + k0 + k] : Wn[(j - EE) * LIN + k0 + k];
        }
        for (int i = tid; i < RTOK * RCH; i += 256) {
            int tt = i / RCH, kk = i % RCH;
            int k = k0 + kk;
            int n = tb + tt;
            float v;
            if (k < DD)        v = x[n * DD + k];
            else if (k < 544)  v = cemb[city[n / TT] * CEC + (k - DD)];
            else if (k < 672)  v = dt[n * 128 + (k - 544)];
            else if (k < 800)  v = dd[n * 128 + (k - 672)];
            else if (k < 864)  v = dr[n * 64 + (k - 800)];
            else               v = de[n * 64 + (k - 864)];
            hsh[tt][kk] = v;
        }
        __syncthreads();
        for (int k = 0; k < RCH; k++) {
            float a = hsh[t][k];
            acc0 += a * Wsh[s][k];
            acc1 += a * Wsh[s + 8][k];
            if (s < 4) acc2 += a * Wsh[s + 16][k];
        }
        __syncthreads();
    }
    lg[t][s] = acc0;
    lg[t][s + 8] = acc1;
    if (s < 4) lg[t][s + 16] = acc2;
    __syncthreads();

    if (s == 0) {
        const int n = tb + t;
        float logits[EE], noisy[EE], ex[EE];
        float mx = -1e30f;
        for (int e = 0; e < EE; e++) { logits[e] = lg[t][e] + bg[e]; mx = fmaxf(mx, logits[e]); }
        float ssum = 0.f;
        for (int e = 0; e < EE; e++) { ex[e] = expf(logits[e] - mx); ssum += ex[e]; }
        const float rinv = 1.f / ssum;
        for (int e = 0; e < EE; e++) gate1[n * EE + e] = ex[e] * rinv;

        for (int e = 0; e < EE; e++) {
            const float z  = lg[t][EE + e] + bn[e];
            const float sp = fmaxf(z, 0.f) + log1pf(expf(-fabsf(z)));  // stable softplus
            noisy[e] = logits[e] + noise[n * EE + e] * sp;
        }
        int i0 = 0;
        for (int e = 1; e < EE; e++) if (noisy[e] > noisy[i0]) i0 = e;
        int i1 = (i0 == 0) ? 1 : 0;
        for (int e = 0; e < EE; e++) if (e != i0 && noisy[e] > noisy[i1]) i1 = e;

        const float m  = fmaxf(noisy[i0], noisy[i1]);
        const float s0 = expf(noisy[i0] - m), s1 = expf(noisy[i1] - m);
        const float inv = 1.f / (s0 + s1);

        int p0 = atomicAdd(&g_count[i0], 1);
        g_entry[i0 * NTOK + p0] = 2 * n;
        g_wt[i0 * NTOK + p0]    = s0 * inv;
        int p1 = atomicAdd(&g_count[i1], 1);
        g_entry[i1 * NTOK + p1] = 2 * n + 1;
        g_wt[i1 * NTOK + p1]    = s1 * inv;
    }
}

// ---------------------------------------------------------------------------
// Gathered expert GEMM: mma.sync m16n8k16 bf16, 3xBF16 split, fp32 accum.
// All operands pre-split to bf16 hi/lo in gmem; fills are pure cp.async.
//   IS_FFN2 == false: hid(hi,lo)[pair] = split(gelu(x[tok] @ W1[e] + b1[e]))
//   IS_FFN2 == true : out[tok] += w * (hid[pair] @ W2[e] + b2[e])
// Block 128x128, BK=32 (2 k-steps of 16), 8 warps 4x2, warp tile 32x64.
// 2 CTAs/SM; 3-stage cp.async pipeline (fills get 2 compute-stages of slack);
// MMA issue interleaved across 4 independent chains (dep distance 4).
// ---------------------------------------------------------------------------
template<int KTOT, int LDW, bool IS_FFN2>
__global__ __launch_bounds__(256, 2)
void moe_mma_kernel(const float* __restrict__ bias,
                    float* __restrict__ outp)
{
    constexpr int NT = KTOT / BK;
    const int e  = blockIdx.z;
    const int m0 = blockIdx.y * BM;
    const int n0 = blockIdx.x * BN;
    const int L  = g_count[e];
    if (m0 >= L) return;

    extern __shared__ char smem[];
    __shared__ int   toks[BM];
    __shared__ float wts[BM];

    const int tid  = threadIdx.x;
    const int wid  = tid >> 5;
    const int lane = tid & 31;

    if (tid < BM) {
        int i = m0 + tid;
        toks[tid] = (i < L) ? g_entry[e * NTOK + i] : -1;
        wts[tid]  = (IS_FFN2 && i < L) ? g_wt[e * NTOK + i] : 0.f;
    }
    __syncthreads();

    const char* Ah = IS_FFN2 ? (const char*)g_hid_h : (const char*)g_xh;
    const char* Al = IS_FFN2 ? (const char*)g_hid_l : (const char*)g_xl;
    const char* Wh = IS_FFN2 ? (const char*)g_w2h : (const char*)g_w1h;
    const char* Wl = IS_FFN2 ? (const char*)g_w2l : (const char*)g_w1l;

    // ---- cp.async fills ----
    auto fill_stage = [&](int buf, int k0) {
        char* st = smem + buf * STAGE;
        // A: 128 rows x 4 chunks of 16B, hi+lo; 2 passes
        #pragma unroll
        for (int p = 0; p < 2; p++) {
            const int idx = p * 256 + tid;
            const int r = idx >> 2, c = idx & 3;
            const int ent = toks[r];
            const int row = ent >= 0 ? (IS_FFN2 ? ent : (ent >> 1)) : 0;
            const uint32_t sz = ent >= 0 ? 16u : 0u;
            const size_t so = ((size_t)row * KTOT + k0 + c * 8) * 2;
            CPA(sm_u32(st + OFF_AH + r * 80 + c * 16), Ah + so, sz);
            CPA(sm_u32(st + OFF_AL + r * 80 + c * 16), Al + so, sz);
        }
        // B: 32 k-rows x 16 chunks of 16B, hi+lo; 2 passes
        const size_t wbase = ((size_t)e * KTOT + k0) * LDW + n0;
        #pragma unroll
        for (int p = 0; p < 2; p++) {
            const int idx = p * 256 + tid;
            const int k = idx >> 4, c = idx & 15;
            const size_t so = (wbase + (size_t)k * LDW + c * 8) * 2;
            const int doff = k * 256 + ((c ^ (k & 7)) * 16);
            CPB(sm_u32(st + OFF_BH + doff), Wh + so);
            CPB(sm_u32(st + OFF_BL + doff), Wl + so);
        }
    };

    // ---- accumulators ----
    const int wm = wid >> 1, wn = wid & 1;
    float acc[2][8][4];
    #pragma unroll
    for (int mt = 0; mt < 2; mt++)
        #pragma unroll
        for (int nn = 0; nn < 8; nn++)
            #pragma unroll
            for (int i = 0; i < 4; i++) acc[mt][nn][i] = 0.f;

    auto compute_stage = [&](int buf) {
        char* st = smem + buf * STAGE;
        const uint32_t ah = sm_u32(st + OFF_AH);
        const uint32_t al = sm_u32(st + OFF_AL);
        const uint32_t bh = sm_u32(st + OFF_BH);
        const uint32_t bl = sm_u32(st + OFF_BL);
        #pragma unroll
        for (int ks = 0; ks < 2; ks++) {
            // A frags: rows lane&15, k-half lane>>4
            uint32_t a_h[2][4], a_l[2][4];
            #pragma unroll
            for (int mt = 0; mt < 2; mt++) {
                const uint32_t ao = (wm * 32 + mt * 16 + (lane & 15)) * 80
                                  + ks * 32 + (lane >> 4) * 16;
                LDSM_X4(a_h[mt][0], a_h[mt][1], a_h[mt][2], a_h[mt][3], ah + ao);
                LDSM_X4(a_l[mt][0], a_l[mt][1], a_l[mt][2], a_l[mt][3], al + ao);
            }
            // B frags per-bt; MMAs interleaved across 4 chains (2 mt x d0/d1)
            #pragma unroll
            for (int bt = 0; bt < 4; bt++) {
                uint32_t bfh[4], bfl[4];
                const int k = ks * 16 + (lane & 15);
                const int c = ((wn * 64 + bt * 16) >> 3) + (lane >> 4);
                const uint32_t bo = k * 256 + ((c ^ (lane & 7)) * 16);
                LDSM_X4T(bfh[0], bfh[1], bfh[2], bfh[3], bh + bo);
                LDSM_X4T(bfl[0], bfl[1], bfl[2], bfl[3], bl + bo);
                // term 1: Ah*Bh  (4 independent MMAs)
                #pragma unroll
                for (int mt = 0; mt < 2; mt++) {
                    MMA_BF16(acc[mt][2 * bt],     a_h[mt][0], a_h[mt][1], a_h[mt][2], a_h[mt][3], bfh[0], bfh[1]);
                    MMA_BF16(acc[mt][2 * bt + 1], a_h[mt][0], a_h[mt][1], a_h[mt][2], a_h[mt][3], bfh[2], bfh[3]);
                }
                // term 2: Ah*Bl
                #pragma unroll
                for (int mt = 0; mt < 2; mt++) {
                    MMA_BF16(acc[mt][2 * bt],     a_h[mt][0], a_h[mt][1], a_h[mt][2], a_h[mt][3], bfl[0], bfl[1]);
                    MMA_BF16(acc[mt][2 * bt + 1], a_h[mt][0], a_h[mt][1], a_h[mt][2], a_h[mt][3], bfl[2], bfl[3]);
                }
                // term 3: Al*Bh
                #pragma unroll
                for (int mt = 0; mt < 2; mt++) {
                    MMA_BF16(acc[mt][2 * bt],     a_l[mt][0], a_l[mt][1], a_l[mt][2], a_l[mt][3], bfh[0], bfh[1]);
                    MMA_BF16(acc[mt][2 * bt + 1], a_l[mt][0], a_l[mt][1], a_l[mt][2], a_l[mt][3], bfh[2], bfh[3]);
                }
            }
        }
    };

    // ---- mainloop: 3-stage pipeline ----
    fill_stage(0, 0);
    CP_COMMIT();
    if (NT > 1) { fill_stage(1, BK); CP_COMMIT(); }
    int buf = 0, nxt = (NT > 1) ? 2 : 1;
    for (int t = 0; t < NT; t++) {
        if (t + 1 < NT) CP_WAIT1(); else CP_WAIT0();
        __syncthreads();
        if (t + 2 < NT) {
            fill_stage(nxt, (t + 2) * BK);
            CP_COMMIT();
            if (++nxt == NSTAGE) nxt = 0;
        }
        compute_stage(buf);
        if (++buf == NSTAGE) buf = 0;
    }

    // ---- epilogue ----
    const int g  = lane >> 2;
    const int kq = lane & 3;
    const float* be = bias + e * LDW;
    #pragma unroll
    for (int mt = 0; mt < 2; mt++) {
        const int lr0  = wm * 32 + mt * 16 + g;
        const int ent0 = toks[lr0];
        const int ent1 = toks[lr0 + 8];
        #pragma unroll
        for (int nn = 0; nn < 8; nn++) {
            const int c = n0 + wn * 64 + nn * 8 + 2 * kq;
            const float bb0 = be[c], bb1 = be[c + 1];
            if (!IS_FFN2) {
                if (ent0 >= 0) {
                    float v0 = acc[mt][nn][0] + bb0;
                    float v1 = acc[mt][nn][1] + bb1;
                    v0 = 0.5f * v0 * (1.f + erff(v0 * 0.70710678118654752f));
                    v1 = 0.5f * v1 * (1.f + erff(v1 * 0.70710678118654752f));
                    uint32_t h0, l0, h1, l1;
                    bsplit(v0, h0, l0); bsplit(v1, h1, l1);
                    const size_t o = ((size_t)ent0 * HH + c) * 2;
                    *(uint32_t*)((char*)g_hid_h + o) = h0 | (h1 << 16);
                    *(uint32_t*)((char*)g_hid_l + o) = l0 | (l1 << 16);
                }
                if (ent1 >= 0) {
                    float v0 = acc[mt][nn][2] + bb0;
                    float v1 = acc[mt][nn][3] + bb1;
                    v0 = 0.5f * v0 * (1.f + erff(v0 * 0.70710678118654752f));
                    v1 = 0.5f * v1 * (1.f + erff(v1 * 0.70710678118654752f));
                    uint32_t h0, l0, h1, l1;
                    bsplit(v0, h0, l0); bsplit(v1, h1, l1);
                    const size_t o = ((size_t)ent1 * HH + c) * 2;
                    *(uint32_t*)((char*)g_hid_h + o) = h0 | (h1 << 16);
                    *(uint32_t*)((char*)g_hid_l + o) = l0 | (l1 << 16);
                }
            } else {
                if (ent0 >= 0) {
                    const float w = wts[lr0];
                    float* o = outp + (size_t)(ent0 >> 1) * DD + c;
                    atomicAdd(o,     w * (acc[mt][nn][0] + bb0));
                    atomicAdd(o + 1, w * (acc[mt][nn][1] + bb1));
                }
                if (ent1 >= 0) {
                    const float w = wts[lr0 + 8];
                    float* o = outp + (size_t)(ent1 >> 1) * DD + c;
                    atomicAdd(o,     w * (acc[mt][nn][2] + bb0));
                    atomicAdd(o + 1, w * (acc[mt][nn][3] + bb1));
                }
            }
        }
    }
}

// ---------------------------------------------------------------------------
extern "C" void kernel_launch(void* const* d_in, const int* in_sizes, int n_in,
                              void* d_out, int out_size)
{
    const float* x    = (const float*)d_in[0];
    const float* dt   = (const float*)d_in[1];
    const float* dd   = (const float*)d_in[2];
    const float* dr   = (const float*)d_in[3];
    const float* de   = (const float*)d_in[4];
    const float* cemb = (const float*)d_in[5];
    const float* Wg   = (const float*)d_in[6];
    const float* bg   = (const float*)d_in[7];
    const float* Wn   = (const float*)d_in[8];
    const float* bn   = (const float*)d_in[9];
    const float* W1   = (const float*)d_in[10];
    const float* b1   = (const float*)d_in[11];
    const float* W2   = (const float*)d_in[12];
    const float* b2   = (const float*)d_in[13];
    const float* noise= (const float*)d_in[14];
    const int*   city = (const int*)d_in[15];

    float* out   = (float*)d_out;                       // (4096, 512)
    float* gate1 = (float*)d_out + (size_t)NTOK * DD;   // (4096, 10)

    cudaFuncSetAttribute((const void*)moe_mma_kernel<DD, HH, false>,
                         cudaFuncAttributeMaxDynamicSharedMemorySize, SMEM_DYN);
    cudaFuncSetAttribute((const void*)moe_mma_kernel<HH, DD, true>,
                         cudaFuncAttributeMaxDynamicSharedMemorySize, SMEM_DYN);

    cudaMemsetAsync(d_out, 0, (size_t)NTOK * DD * sizeof(float));
    zero_counts_kernel<<<1, 32>>>();

    // pre-split operands to bf16 hi/lo (once)
    {
        __nv_bfloat16 *xh, *xl, *w1h, *w1l, *w2h, *w2l;
        cudaGetSymbolAddress((void**)&xh,  g_xh);
        cudaGetSymbolAddress((void**)&xl,  g_xl);
        cudaGetSymbolAddress((void**)&w1h, g_w1h);
        cudaGetSymbolAddress((void**)&w1l, g_w1l);
        cudaGetSymbolAddress((void**)&w2h, g_w2h);
        cudaGetSymbolAddress((void**)&w2l, g_w2l);
        const int nx = NTOK * DD / 4;
        const int nw = EE * DD * HH / 4;
        presplit_kernel<<<(nx + 255) / 256, 256>>>(x,  xh,  xl,  nx);
        presplit_kernel<<<(nw + 255) / 256, 256>>>(W1, w1h, w1l, nw);
        presplit_kernel<<<(nw + 255) / 256, 256>>>(W2, w2h, w2l, nw);
    }

    router_kernel<<<NTOK / RTOK, 256>>>(x, dt, dd, dr, de, cemb, Wg, bg, Wn, bn,
                                        noise, city, gate1);

    dim3 grid1(HH / BN, NTOK / BM, EE);   // (16, 32, 10)
    moe_mma_kernel<DD, HH, false><<<grid1, 256, SMEM_DYN>>>(b1, nullptr);

    dim3 grid2(DD / BN, NTOK / BM, EE);   // (4, 32, 10)
    moe_mma_kernel<HH, DD, true><<<grid2, 256, SMEM_DYN>>>(b2, out);
}

// round 14
// speedup vs baseline: 1.0389x; 1.0388x over previous
#include <cuda_runtime.h>
#include <cuda_bf16.h>
#include <math.h>
#include <stdint.h>

#define TT 1024
#define DD 512
#define EE 10
#define HH 2048
#define CEC 32
#define LIN 928
#define NTOK 4096
#define NPAIR 8192

#define BM 128
#define BN 128
#define BK 32           // bf16 k per stage

// A tile: 128 rows x 32 bf16, 80B pitch (conflict-free ldmatrix) = 10240B
// B tile: 32 k-rows x 128 bf16, 256B pitch, chunk-XOR swizzle = 8192B
#define A_TILE 10240
#define B_TILE 8192
#define OFF_AH 0
#define OFF_AL A_TILE
#define OFF_BH (2 * A_TILE)
#define OFF_BL (2 * A_TILE + B_TILE)
#define STAGE  (2 * A_TILE + 2 * B_TILE)   // 36864
#define NSTAGE 3
#define SMEM_DYN (NSTAGE * STAGE)          // 110592 (2 CTAs/SM)

// Scratch (static device arrays — no allocation allowed)
__device__ __align__(16) __nv_bfloat16 g_hid_h[(size_t)NPAIR * HH];   // 32 MB
__device__ __align__(16) __nv_bfloat16 g_hid_l[(size_t)NPAIR * HH];   // 32 MB
__device__ __align__(16) __nv_bfloat16 g_xh[(size_t)NTOK * DD];
__device__ __align__(16) __nv_bfloat16 g_xl[(size_t)NTOK * DD];
__device__ __align__(16) __nv_bfloat16 g_w1h[(size_t)EE * DD * HH];
__device__ __align__(16) __nv_bfloat16 g_w1l[(size_t)EE * DD * HH];
__device__ __align__(16) __nv_bfloat16 g_w2h[(size_t)EE * HH * DD];
__device__ __align__(16) __nv_bfloat16 g_w2l[(size_t)EE * HH * DD];
__device__ int   g_count[EE];
__device__ int   g_entry[EE * NTOK];          // packed: token*2 + slot
__device__ float g_wt[EE * NTOK];

__global__ void zero_counts_kernel() {
    if (threadIdx.x < EE) g_count[threadIdx.x] = 0;
}

// ---------------------------------------------------------------------------
// helpers
// ---------------------------------------------------------------------------
__device__ __forceinline__ uint32_t sm_u32(const void* p) {
    return (uint32_t)__cvta_generic_to_shared(p);
}
__device__ __forceinline__ void bsplit(float v, uint32_t& h, uint32_t& l) {
    __nv_bfloat16 bh = __float2bfloat16_rn(v);
    h = (uint32_t)__bfloat16_as_ushort(bh);
    l = (uint32_t)__bfloat16_as_ushort(__float2bfloat16_rn(v - __bfloat162float(bh)));
}

#define MMA_BF16(d, a0, a1, a2, a3, b0, b1)                                   \
    asm volatile(                                                             \
        "mma.sync.aligned.m16n8k16.row.col.f32.bf16.bf16.f32 "                \
        "{%0,%1,%2,%3}, {%4,%5,%6,%7}, {%8,%9}, {%0,%1,%2,%3};"               \
        : "+f"((d)[0]), "+f"((d)[1]), "+f"((d)[2]), "+f"((d)[3])              \
        : "r"(a0), "r"(a1), "r"(a2), "r"(a3), "r"(b0), "r"(b1))

#define LDSM_X4(r0, r1, r2, r3, addr)                                         \
    asm volatile("ldmatrix.sync.aligned.m8n8.x4.shared.b16 {%0,%1,%2,%3}, [%4];" \
        : "=r"(r0), "=r"(r1), "=r"(r2), "=r"(r3) : "r"(addr))

#define LDSM_X4T(r0, r1, r2, r3, addr)                                        \
    asm volatile("ldmatrix.sync.aligned.m8n8.x4.trans.shared.b16 {%0,%1,%2,%3}, [%4];" \
        : "=r"(r0), "=r"(r1), "=r"(r2), "=r"(r3) : "r"(addr))

// all fills .cg: bypass L1 so the 3-stage smem footprint's L1-carveout
// shrink cannot hurt the fill path
#define CPA(dst, src, sz)                                                     \
    asm volatile("cp.async.cg.shared.global [%0], [%1], 16, %2;"              \
        :: "r"(dst), "l"(src), "r"(sz) : "memory")
#define CPB(dst, src)                                                         \
    asm volatile("cp.async.cg.shared.global [%0], [%1], 16;"                  \
        :: "r"(dst), "l"(src) : "memory")
#define CP_COMMIT() asm volatile("cp.async.commit_group;" ::: "memory")
#define CP_WAIT0()  asm volatile("cp.async.wait_group 0;" ::: "memory")
#define CP_WAIT1()  asm volatile("cp.async.wait_group 1;" ::: "memory")

// ---------------------------------------------------------------------------
// Pre-split: fp32 -> bf16 hi/lo pair, vectorized float4.
// ---------------------------------------------------------------------------
__global__ __launch_bounds__(256)
void presplit_kernel(const float* __restrict__ src,
                     __nv_bfloat16* __restrict__ h,
                     __nv_bfloat16* __restrict__ l, int n4)
{
    int i = blockIdx.x * 256 + threadIdx.x;
    if (i >= n4) return;
    float4 v = ((const float4*)src)[i];
    uint32_t hh[4], ll[4];
    bsplit(v.x, hh[0], ll[0]); bsplit(v.y, hh[1], ll[1]);
    bsplit(v.z, hh[2], ll[2]); bsplit(v.w, hh[3], ll[3]);
    ((uint2*)h)[i] = make_uint2(hh[0] | (hh[1] << 16), hh[2] | (hh[3] << 16));
    ((uint2*)l)[i] = make_uint2(ll[0] | (ll[1] << 16), ll[2] | (ll[3] << 16));
}

// ---------------------------------------------------------------------------
// Router: 32 tokens per block, weights staged in smem.
// ---------------------------------------------------------------------------
#define RTOK 32
#define RCH 116   // 928 / 8 chunks

__global__ __launch_bounds__(256)
void router_kernel(const float* __restrict__ x,
                   const float* __restrict__ dt,
                   const float* __restrict__ dd,
                   const float* __restrict__ dr,
                   const float* __restrict__ de,
                   const float* __restrict__ cemb,
                   const float* __restrict__ Wg,
                   const float* __restrict__ bg,
                   const float* __restrict__ Wn,
                   const float* __restrict__ bn,
                   const float* __restrict__ noise,
                   const int*   __restrict__ city,
                   float* __restrict__ gate1)
{
    __shared__ float Wsh[2 * EE][RCH];
    __shared__ float hsh[RTOK][RCH];
    __shared__ float lg[RTOK][2 * EE];

    const int tid = threadIdx.x;          // 256
    const int tb = blockIdx.x * RTOK;
    const int t = tid >> 3;               // token slot 0..31
    const int s = tid & 7;                // 0..7

    float acc0 = 0.f, acc1 = 0.f, acc2 = 0.f;

    for (int c = 0; c < 8; c++) {
        const int k0 = c * RCH;
        for (int i = tid; i < 2 * EE * RCH; i += 256) {
            int j = i / RCH, k = i % RCH;
            Wsh[j][k] = (j < EE) ? Wg[j * LIN + k0 + k] : Wn[(j - EE) * LIN + k0 + k];
        }
        for (int i = tid; i < RTOK * RCH; i += 256) {
            int tt = i / RCH, kk = i % RCH;
            int k = k0 + kk;
            int n = tb + tt;
            float v;
            if (k < DD)        v = x[n * DD + k];
            else if (k < 544)  v = cemb[city[n / TT] * CEC + (k - DD)];
            else if (k < 672)  v = dt[n * 128 + (k - 544)];
            else if (k < 800)  v = dd[n * 128 + (k - 672)];
            else if (k < 864)  v = dr[n * 64 + (k - 800)];
            else               v = de[n * 64 + (k - 864)];
            hsh[tt][kk] = v;
        }
        __syncthreads();
        for (int k = 0; k < RCH; k++) {
            float a = hsh[t][k];
            acc0 += a * Wsh[s][k];
            acc1 += a * Wsh[s + 8][k];
            if (s < 4) acc2 += a * Wsh[s + 16][k];
        }
        __syncthreads();
    }
    lg[t][s] = acc0;
    lg[t][s + 8] = acc1;
    if (s < 4) lg[t][s + 16] = acc2;
    __syncthreads();

    if (s == 0) {
        const int n = tb + t;
        float logits[EE], noisy[EE], ex[EE];
        float mx = -1e30f;
        for (int e = 0; e < EE; e++) { logits[e] = lg[t][e] + bg[e]; mx = fmaxf(mx, logits[e]); }
        float ssum = 0.f;
        for (int e = 0; e < EE; e++) { ex[e] = expf(logits[e] - mx); ssum += ex[e]; }
        const float rinv = 1.f / ssum;
        for (int e = 0; e < EE; e++) gate1[n * EE + e] = ex[e] * rinv;

        for (int e = 0; e < EE; e++) {
            const float z  = lg[t][EE + e] + bn[e];
            const float sp = fmaxf(z, 0.f) + log1pf(expf(-fabsf(z)));  // stable softplus
            noisy[e] = logits[e] + noise[n * EE + e] * sp;
        }
        int i0 = 0;
        for (int e = 1; e < EE; e++) if (noisy[e] > noisy[i0]) i0 = e;
        int i1 = (i0 == 0) ? 1 : 0;
        for (int e = 0; e < EE; e++) if (e != i0 && noisy[e] > noisy[i1]) i1 = e;

        const float m  = fmaxf(noisy[i0], noisy[i1]);
        const float s0 = expf(noisy[i0] - m), s1 = expf(noisy[i1] - m);
        const float inv = 1.f / (s0 + s1);

        int p0 = atomicAdd(&g_count[i0], 1);
        g_entry[i0 * NTOK + p0] = 2 * n;
        g_wt[i0 * NTOK + p0]    = s0 * inv;
        int p1 = atomicAdd(&g_count[i1], 1);
        g_entry[i1 * NTOK + p1] = 2 * n + 1;
        g_wt[i1 * NTOK + p1]    = s1 * inv;
    }
}

// ---------------------------------------------------------------------------
// Gathered expert GEMM: mma.sync m16n8k16 bf16, 3xBF16 split, fp32 accum.
// All operands pre-split to bf16 hi/lo in gmem; fills are pure cp.async (.cg).
//   IS_FFN2 == false: hid(hi,lo)[pair] = split(gelu(x[tok] @ W1[e] + b1[e]))
//   IS_FFN2 == true : out[tok] += w * (hid[pair] @ W2[e] + b2[e])
// Block 128x128, BK=32, 8 warps 4x2, warp tile 32x64, 2 CTAs/SM.
// 3-stage cp.async pipeline: each fill gets 2 compute-stages of slack.
// Compute order = proven R10 sequence (no interleave).
// ---------------------------------------------------------------------------
template<int KTOT, int LDW, bool IS_FFN2>
__global__ __launch_bounds__(256, 2)
void moe_mma_kernel(const float* __restrict__ bias,
                    float* __restrict__ outp)
{
    constexpr int NT = KTOT / BK;
    const int e  = blockIdx.z;
    const int m0 = blockIdx.y * BM;
    const int n0 = blockIdx.x * BN;
    const int L  = g_count[e];
    if (m0 >= L) return;

    extern __shared__ char smem[];
    __shared__ int   toks[BM];
    __shared__ float wts[BM];

    const int tid  = threadIdx.x;
    const int wid  = tid >> 5;
    const int lane = tid & 31;

    if (tid < BM) {
        int i = m0 + tid;
        toks[tid] = (i < L) ? g_entry[e * NTOK + i] : -1;
        wts[tid]  = (IS_FFN2 && i < L) ? g_wt[e * NTOK + i] : 0.f;
    }
    __syncthreads();

    const char* Ah = IS_FFN2 ? (const char*)g_hid_h : (const char*)g_xh;
    const char* Al = IS_FFN2 ? (const char*)g_hid_l : (const char*)g_xl;
    const char* Wh = IS_FFN2 ? (const char*)g_w2h : (const char*)g_w1h;
    const char* Wl = IS_FFN2 ? (const char*)g_w2l : (const char*)g_w1l;

    // ---- cp.async fills ----
    auto fill_stage = [&](int buf, int k0) {
        char* st = smem + buf * STAGE;
        // A: 128 rows x 4 chunks of 16B, hi+lo; 2 passes
        #pragma unroll
        for (int p = 0; p < 2; p++) {
            const int idx = p * 256 + tid;
            const int r = idx >> 2, c = idx & 3;
            const int ent = toks[r];
            const int row = ent >= 0 ? (IS_FFN2 ? ent : (ent >> 1)) : 0;
            const uint32_t sz = ent >= 0 ? 16u : 0u;
            const size_t so = ((size_t)row * KTOT + k0 + c * 8) * 2;
            CPA(sm_u32(st + OFF_AH + r * 80 + c * 16), Ah + so, sz);
            CPA(sm_u32(st + OFF_AL + r * 80 + c * 16), Al + so, sz);
        }
        // B: 32 k-rows x 16 chunks of 16B, hi+lo; 2 passes
        const size_t wbase = ((size_t)e * KTOT + k0) * LDW + n0;
        #pragma unroll
        for (int p = 0; p < 2; p++) {
            const int idx = p * 256 + tid;
            const int k = idx >> 4, c = idx & 15;
            const size_t so = (wbase + (size_t)k * LDW + c * 8) * 2;
            const int doff = k * 256 + ((c ^ (k & 7)) * 16);
            CPB(sm_u32(st + OFF_BH + doff), Wh + so);
            CPB(sm_u32(st + OFF_BL + doff), Wl + so);
        }
    };

    // ---- accumulators ----
    const int wm = wid >> 1, wn = wid & 1;
    float acc[2][8][4];
    #pragma unroll
    for (int mt = 0; mt < 2; mt++)
        #pragma unroll
        for (int nn = 0; nn < 8; nn++)
            #pragma unroll
            for (int i = 0; i < 4; i++) acc[mt][nn][i] = 0.f;

    auto compute_stage = [&](int buf) {
        char* st = smem + buf * STAGE;
        const uint32_t ah = sm_u32(st + OFF_AH);
        const uint32_t al = sm_u32(st + OFF_AL);
        const uint32_t bh = sm_u32(st + OFF_BH);
        const uint32_t bl = sm_u32(st + OFF_BL);
        #pragma unroll
        for (int ks = 0; ks < 2; ks++) {
            // A frags: rows lane&15, k-half lane>>4
            uint32_t a_h[2][4], a_l[2][4];
            #pragma unroll
            for (int mt = 0; mt < 2; mt++) {
                const uint32_t ao = (wm * 32 + mt * 16 + (lane & 15)) * 80
                                  + ks * 32 + (lane >> 4) * 16;
                LDSM_X4(a_h[mt][0], a_h[mt][1], a_h[mt][2], a_h[mt][3], ah + ao);
                LDSM_X4(a_l[mt][0], a_l[mt][1], a_l[mt][2], a_l[mt][3], al + ao);
            }
            // B frags loaded per-bt; R10-proven MMA order
            #pragma unroll
            for (int bt = 0; bt < 4; bt++) {
                uint32_t bfh[4], bfl[4];
                const int k = ks * 16 + (lane & 15);
                const int c = ((wn * 64 + bt * 16) >> 3) + (lane >> 4);
                const uint32_t bo = k * 256 + ((c ^ (lane & 7)) * 16);
                LDSM_X4T(bfh[0], bfh[1], bfh[2], bfh[3], bh + bo);
                LDSM_X4T(bfl[0], bfl[1], bfl[2], bfl[3], bl + bo);
                #pragma unroll
                for (int mt = 0; mt < 2; mt++) {
                    float* d0 = acc[mt][2 * bt];
                    float* d1 = acc[mt][2 * bt + 1];
                    MMA_BF16(d0, a_h[mt][0], a_h[mt][1], a_h[mt][2], a_h[mt][3],
                             bfh[0], bfh[1]);
                    MMA_BF16(d0, a_h[mt][0], a_h[mt][1], a_h[mt][2], a_h[mt][3],
                             bfl[0], bfl[1]);
                    MMA_BF16(d0, a_l[mt][0], a_l[mt][1], a_l[mt][2], a_l[mt][3],
                             bfh[0], bfh[1]);
                    MMA_BF16(d1, a_h[mt][0], a_h[mt][1], a_h[mt][2], a_h[mt][3],
                             bfh[2], bfh[3]);
                    MMA_BF16(d1, a_h[mt][0], a_h[mt][1], a_h[mt][2], a_h[mt][3],
                             bfl[2], bfl[3]);
                    MMA_BF16(d1, a_l[mt][0], a_l[mt][1], a_l[mt][2], a_l[mt][3],
                             bfh[2], bfh[3]);
                }
            }
        }
    };

    // ---- mainloop: 3-stage pipeline ----
    fill_stage(0, 0);
    CP_COMMIT();
    if (NT > 1) { fill_stage(1, BK); CP_COMMIT(); }
    int buf = 0, nxt = (NT > 1) ? 2 : 1;
    for (int t = 0; t < NT; t++) {
        if (t + 1 < NT) CP_WAIT1(); else CP_WAIT0();
        __syncthreads();
        if (t + 2 < NT) {
            fill_stage(nxt, (t + 2) * BK);
            CP_COMMIT();
            if (++nxt == NSTAGE) nxt = 0;
        }
        compute_stage(buf);
        if (++buf == NSTAGE) buf = 0;
    }

    // ---- epilogue ----
    const int g  = lane >> 2;
    const int kq = lane & 3;
    const float* be = bias + e * LDW;
    #pragma unroll
    for (int mt = 0; mt < 2; mt++) {
        const int lr0  = wm * 32 + mt * 16 + g;
        const int ent0 = toks[lr0];
        const int ent1 = toks[lr0 + 8];
        #pragma unroll
        for (int nn = 0; nn < 8; nn++) {
            const int c = n0 + wn * 64 + nn * 8 + 2 * kq;
            const float bb0 = be[c], bb1 = be[c + 1];
            if (!IS_FFN2) {
                if (ent0 >= 0) {
                    float v0 = acc[mt][nn][0] + bb0;
                    float v1 = acc[mt][nn][1] + bb1;
                    v0 = 0.5f * v0 * (1.f + erff(v0 * 0.70710678118654752f));
                    v1 = 0.5f * v1 * (1.f + erff(v1 * 0.70710678118654752f));
                    uint32_t h0, l0, h1, l1;
                    bsplit(v0, h0, l0); bsplit(v1, h1, l1);
                    const size_t o = ((size_t)ent0 * HH + c) * 2;
                    *(uint32_t*)((char*)g_hid_h + o) = h0 | (h1 << 16);
                    *(uint32_t*)((char*)g_hid_l + o) = l0 | (l1 << 16);
                }
                if (ent1 >= 0) {
                    float v0 = acc[mt][nn][2] + bb0;
                    float v1 = acc[mt][nn][3] + bb1;
                    v0 = 0.5f * v0 * (1.f + erff(v0 * 0.70710678118654752f));
                    v1 = 0.5f * v1 * (1.f + erff(v1 * 0.70710678118654752f));
                    uint32_t h0, l0, h1, l1;
                    bsplit(v0, h0, l0); bsplit(v1, h1, l1);
                    const size_t o = ((size_t)ent1 * HH + c) * 2;
                    *(uint32_t*)((char*)g_hid_h + o) = h0 | (h1 << 16);
                    *(uint32_t*)((char*)g_hid_l + o) = l0 | (l1 << 16);
                }
            } else {
                if (ent0 >= 0) {
                    const float w = wts[lr0];
                    float* o = outp + (size_t)(ent0 >> 1) * DD + c;
                    atomicAdd(o,     w * (acc[mt][nn][0] + bb0));
                    atomicAdd(o + 1, w * (acc[mt][nn][1] + bb1));
                }
                if (ent1 >= 0) {
                    const float w = wts[lr0 + 8];
                    float* o = outp + (size_t)(ent1 >> 1) * DD + c;
                    atomicAdd(o,     w * (acc[mt][nn][2] + bb0));
                    atomicAdd(o + 1, w * (acc[mt][nn][3] + bb1));
                }
            }
        }
    }
}

// ---------------------------------------------------------------------------
extern "C" void kernel_launch(void* const* d_in, const int* in_sizes, int n_in,
                              void* d_out, int out_size)
{
    const float* x    = (const float*)d_in[0];
    const float* dt   = (const float*)d_in[1];
    const float* dd   = (const float*)d_in[2];
    const float* dr   = (const float*)d_in[3];
    const float* de   = (const float*)d_in[4];
    const float* cemb = (const float*)d_in[5];
    const float* Wg   = (const float*)d_in[6];
    const float* bg   = (const float*)d_in[7];
    const float* Wn   = (const float*)d_in[8];
    const float* bn   = (const float*)d_in[9];
    const float* W1   = (const float*)d_in[10];
    const float* b1   = (const float*)d_in[11];
    const float* W2   = (const float*)d_in[12];
    const float* b2   = (const float*)d_in[13];
    const float* noise= (const float*)d_in[14];
    const int*   city = (const int*)d_in[15];

    float* out   = (float*)d_out;                       // (4096, 512)
    float* gate1 = (float*)d_out + (size_t)NTOK * DD;   // (4096, 10)

    cudaFuncSetAttribute((const void*)moe_mma_kernel<DD, HH, false>,
                         cudaFuncAttributeMaxDynamicSharedMemorySize, SMEM_DYN);
    cudaFuncSetAttribute((const void*)moe_mma_kernel<HH, DD, true>,
                         cudaFuncAttributeMaxDynamicSharedMemorySize, SMEM_DYN);

    cudaMemsetAsync(d_out, 0, (size_t)NTOK * DD * sizeof(float));
    zero_counts_kernel<<<1, 32>>>();

    // pre-split operands to bf16 hi/lo (once)
    {
        __nv_bfloat16 *xh, *xl, *w1h, *w1l, *w2h, *w2l;
        cudaGetSymbolAddress((void**)&xh,  g_xh);
        cudaGetSymbolAddress((void**)&xl,  g_xl);
        cudaGetSymbolAddress((void**)&w1h, g_w1h);
        cudaGetSymbolAddress((void**)&w1l, g_w1l);
        cudaGetSymbolAddress((void**)&w2h, g_w2h);
        cudaGetSymbolAddress((void**)&w2l, g_w2l);
        const int nx = NTOK * DD / 4;
        const int nw = EE * DD * HH / 4;
        presplit_kernel<<<(nx + 255) / 256, 256>>>(x,  xh,  xl,  nx);
        presplit_kernel<<<(nw + 255) / 256, 256>>>(W1, w1h, w1l, nw);
        presplit_kernel<<<(nw + 255) / 256, 256>>>(W2, w2h, w2l, nw);
    }

    router_kernel<<<NTOK / RTOK, 256>>>(x, dt, dd, dr, de, cemb, Wg, bg, Wn, bn,
                                        noise, city, gate1);

    dim3 grid1(HH / BN, NTOK / BM, EE);   // (16, 32, 10)
    moe_mma_kernel<DD, HH, false><<<grid1, 256, SMEM_DYN>>>(b1, nullptr);

    dim3 grid2(DD / BN, NTOK / BM, EE);   // (4, 32, 10)
    moe_mma_kernel<HH, DD, true><<<grid2, 256, SMEM_DYN>>>(b2, out);
}

// round 15
// speedup vs baseline: 1.0601x; 1.0205x over previous
#include <cuda_runtime.h>
#include <cuda_bf16.h>
#include <math.h>
#include <stdint.h>

#define TT 1024
#define DD 512
#define EE 10
#define HH 2048
#define CEC 32
#define LIN 928
#define NTOK 4096
#define NPAIR 8192

#define BM 128
#define BN 128
#define BK 32           // bf16 k per stage

// A tile: 128 rows x 32 bf16, 80B pitch (conflict-free ldmatrix) = 10240B
// B tile: 32 k-rows x 128 bf16, 256B pitch, chunk-XOR swizzle = 8192B
#define A_TILE 10240
#define B_TILE 8192
#define OFF_AH 0
#define OFF_AL A_TILE
#define OFF_BH (2 * A_TILE)
#define OFF_BL (2 * A_TILE + B_TILE)
#define STAGE  (2 * A_TILE + 2 * B_TILE)   // 36864
#define SMEM_DYN (2 * STAGE)               // 73728 (2 CTAs/SM)

// Scratch (static device arrays — no allocation allowed)
__device__ __align__(16) __nv_bfloat16 g_hid_h[(size_t)NPAIR * HH];   // 32 MB
__device__ __align__(16) __nv_bfloat16 g_hid_l[(size_t)NPAIR * HH];   // 32 MB
__device__ __align__(16) __nv_bfloat16 g_xh[(size_t)NTOK * DD];
__device__ __align__(16) __nv_bfloat16 g_xl[(size_t)NTOK * DD];
__device__ __align__(16) __nv_bfloat16 g_w1h[(size_t)EE * DD * HH];
__device__ __align__(16) __nv_bfloat16 g_w1l[(size_t)EE * DD * HH];
__device__ __align__(16) __nv_bfloat16 g_w2h[(size_t)EE * HH * DD];
__device__ __align__(16) __nv_bfloat16 g_w2l[(size_t)EE * HH * DD];
__device__ int   g_count[EE];
__device__ int   g_entry[EE * NTOK];          // packed: token*2 + slot
__device__ float g_wt[EE * NTOK];

__global__ void zero_counts_kernel() {
    if (threadIdx.x < EE) g_count[threadIdx.x] = 0;
}

// ---------------------------------------------------------------------------
// helpers
// ---------------------------------------------------------------------------
__device__ __forceinline__ uint32_t sm_u32(const void* p) {
    return (uint32_t)__cvta_generic_to_shared(p);
}
__device__ __forceinline__ void bsplit(float v, uint32_t& h, uint32_t& l) {
    __nv_bfloat16 bh = __float2bfloat16_rn(v);
    h = (uint32_t)__bfloat16_as_ushort(bh);
    l = (uint32_t)__bfloat16_as_ushort(__float2bfloat16_rn(v - __bfloat162float(bh)));
}

#define MMA_BF16(d, a0, a1, a2, a3, b0, b1)                                   \
    asm volatile(                                                             \
        "mma.sync.aligned.m16n8k16.row.col.f32.bf16.bf16.f32 "                \
        "{%0,%1,%2,%3}, {%4,%5,%6,%7}, {%8,%9}, {%0,%1,%2,%3};"               \
        : "+f"((d)[0]), "+f"((d)[1]), "+f"((d)[2]), "+f"((d)[3])              \
        : "r"(a0), "r"(a1), "r"(a2), "r"(a3), "r"(b0), "r"(b1))

#define LDSM_X4(r0, r1, r2, r3, addr)                                         \
    asm volatile("ldmatrix.sync.aligned.m8n8.x4.shared.b16 {%0,%1,%2,%3}, [%4];" \
        : "=r"(r0), "=r"(r1), "=r"(r2), "=r"(r3) : "r"(addr))

#define LDSM_X4T(r0, r1, r2, r3, addr)                                        \
    asm volatile("ldmatrix.sync.aligned.m8n8.x4.trans.shared.b16 {%0,%1,%2,%3}, [%4];" \
        : "=r"(r0), "=r"(r1), "=r"(r2), "=r"(r3) : "r"(addr))

// cp.async: A uses .ca (L1, co-resident CTAs share m-tile), B uses .cg (L2 only)
#define CPA(dst, src, sz)                                                     \
    asm volatile("cp.async.ca.shared.global [%0], [%1], 16, %2;"              \
        :: "r"(dst), "l"(src), "r"(sz) : "memory")
#define CPB(dst, src)                                                         \
    asm volatile("cp.async.cg.shared.global [%0], [%1], 16;"                  \
        :: "r"(dst), "l"(src) : "memory")
#define CP_COMMIT() asm volatile("cp.async.commit_group;" ::: "memory")
#define CP_WAIT0()  asm volatile("cp.async.wait_group 0;" ::: "memory")

// ---------------------------------------------------------------------------
// Fused pre-split: x, W1, W2 -> bf16 hi/lo in one launch.
// Segments: [0, nx) -> x ; [nx, nx+nw) -> W1 ; [nx+nw, nx+2nw) -> W2.
// ---------------------------------------------------------------------------
__global__ __launch_bounds__(256)
void presplit_all_kernel(const float* __restrict__ x,
                         const float* __restrict__ W1,
                         const float* __restrict__ W2)
{
    const int nx = NTOK * DD / 4;
    const int nw = EE * DD * HH / 4;
    int i = blockIdx.x * 256 + threadIdx.x;
    const float* src;
    __nv_bfloat16 *h, *l;
    int j;
    if (i < nx)                { src = x;  h = g_xh;  l = g_xl;  j = i; }
    else if (i < nx + nw)      { src = W1; h = g_w1h; l = g_w1l; j = i - nx; }
    else if (i < nx + 2 * nw)  { src = W2; h = g_w2h; l = g_w2l; j = i - nx - nw; }
    else return;

    float4 v = ((const float4*)src)[j];
    uint32_t hh[4], ll[4];
    bsplit(v.x, hh[0], ll[0]); bsplit(v.y, hh[1], ll[1]);
    bsplit(v.z, hh[2], ll[2]); bsplit(v.w, hh[3], ll[3]);
    ((uint2*)h)[j] = make_uint2(hh[0] | (hh[1] << 16), hh[2] | (hh[3] << 16));
    ((uint2*)l)[j] = make_uint2(ll[0] | (ll[1] << 16), ll[2] | (ll[3] << 16));
}

// ---------------------------------------------------------------------------
// Router: 32 tokens per block, weights staged in smem.
// ---------------------------------------------------------------------------
#define RTOK 32
#define RCH 116   // 928 / 8 chunks

__global__ __launch_bounds__(256)
void router_kernel(const float* __restrict__ x,
                   const float* __restrict__ dt,
                   const float* __restrict__ dd,
                   const float* __restrict__ dr,
                   const float* __restrict__ de,
                   const float* __restrict__ cemb,
                   const float* __restrict__ Wg,
                   const float* __restrict__ bg,
                   const float* __restrict__ Wn,
                   const float* __restrict__ bn,
                   const float* __restrict__ noise,
                   const int*   __restrict__ city,
                   float* __restrict__ gate1)
{
    __shared__ float Wsh[2 * EE][RCH];
    __shared__ float hsh[RTOK][RCH];
    __shared__ float lg[RTOK][2 * EE];

    const int tid = threadIdx.x;          // 256
    const int tb = blockIdx.x * RTOK;
    const int t = tid >> 3;               // token slot 0..31
    const int s = tid & 7;                // 0..7

    float acc0 = 0.f, acc1 = 0.f, acc2 = 0.f;

    for (int c = 0; c < 8; c++) {
        const int k0 = c * RCH;
        for (int i = tid; i < 2 * EE * RCH; i += 256) {
            int j = i / RCH, k = i % RCH;
            Wsh[j][k] = (j < EE) ? Wg[j * LIN + k0 + k] : Wn[(j - EE) * LIN + k0 + k];
        }
        for (int i = tid; i < RTOK * RCH; i += 256) {
            int tt = i / RCH, kk = i % RCH;
            int k = k0 + kk;
            int n = tb + tt;
            float v;
            if (k < DD)        v = x[n * DD + k];
            else if (k < 544)  v = cemb[city[n / TT] * CEC + (k - DD)];
            else if (k < 672)  v = dt[n * 128 + (k - 544)];
            else if (k < 800)  v = dd[n * 128 + (k - 672)];
            else if (k < 864)  v = dr[n * 64 + (k - 800)];
            else               v = de[n * 64 + (k - 864)];
            hsh[tt][kk] = v;
        }
        __syncthreads();
        for (int k = 0; k < RCH; k++) {
            float a = hsh[t][k];
            acc0 += a * Wsh[s][k];
            acc1 += a * Wsh[s + 8][k];
            if (s < 4) acc2 += a * Wsh[s + 16][k];
        }
        __syncthreads();
    }
    lg[t][s] = acc0;
    lg[t][s + 8] = acc1;
    if (s < 4) lg[t][s + 16] = acc2;
    __syncthreads();

    if (s == 0) {
        const int n = tb + t;
        float logits[EE], noisy[EE], ex[EE];
        float mx = -1e30f;
        for (int e = 0; e < EE; e++) { logits[e] = lg[t][e] + bg[e]; mx = fmaxf(mx, logits[e]); }
        float ssum = 0.f;
        for (int e = 0; e < EE; e++) { ex[e] = expf(logits[e] - mx); ssum += ex[e]; }
        const float rinv = 1.f / ssum;
        for (int e = 0; e < EE; e++) gate1[n * EE + e] = ex[e] * rinv;

        for (int e = 0; e < EE; e++) {
            const float z  = lg[t][EE + e] + bn[e];
            const float sp = fmaxf(z, 0.f) + log1pf(expf(-fabsf(z)));  // stable softplus
            noisy[e] = logits[e] + noise[n * EE + e] * sp;
        }
        int i0 = 0;
        for (int e = 1; e < EE; e++) if (noisy[e] > noisy[i0]) i0 = e;
        int i1 = (i0 == 0) ? 1 : 0;
        for (int e = 0; e < EE; e++) if (e != i0 && noisy[e] > noisy[i1]) i1 = e;

        const float m  = fmaxf(noisy[i0], noisy[i1]);
        const float s0 = expf(noisy[i0] - m), s1 = expf(noisy[i1] - m);
        const float inv = 1.f / (s0 + s1);

        int p0 = atomicAdd(&g_count[i0], 1);
        g_entry[i0 * NTOK + p0] = 2 * n;
        g_wt[i0 * NTOK + p0]    = s0 * inv;
        int p1 = atomicAdd(&g_count[i1], 1);
        g_entry[i1 * NTOK + p1] = 2 * n + 1;
        g_wt[i1 * NTOK + p1]    = s1 * inv;
    }
}

// ---------------------------------------------------------------------------
// Gathered expert GEMM: mma.sync m16n8k16 bf16, 3xBF16 split, fp32 accum.
// All operands pre-split to bf16 hi/lo in gmem; fills are pure cp.async.
//   IS_FFN2 == false: hid(hi,lo)[pair] = split(gelu(x[tok] @ W1[e] + b1[e]))
//   IS_FFN2 == true : out[tok] += w * (hid[pair] @ W2[e] + b2[e])
// Block 128x128, BK=32, 8 warps 4x2, warp tile 32x64, 2 CTAs/SM.
// R10 2-stage pipeline; MMA order interleaved term-major across the 4
// independent accumulator chains (dep distance 4 instead of 1).
// ---------------------------------------------------------------------------
template<int KTOT, int LDW, bool IS_FFN2>
__global__ __launch_bounds__(256, 2)
void moe_mma_kernel(const float* __restrict__ bias,
                    float* __restrict__ outp)
{
    constexpr int NT = KTOT / BK;
    const int e  = blockIdx.z;
    const int m0 = blockIdx.y * BM;
    const int n0 = blockIdx.x * BN;
    const int L  = g_count[e];
    if (m0 >= L) return;

    extern __shared__ char smem[];
    __shared__ int   toks[BM];
    __shared__ float wts[BM];

    const int tid  = threadIdx.x;
    const int wid  = tid >> 5;
    const int lane = tid & 31;

    if (tid < BM) {
        int i = m0 + tid;
        toks[tid] = (i < L) ? g_entry[e * NTOK + i] : -1;
        wts[tid]  = (IS_FFN2 && i < L) ? g_wt[e * NTOK + i] : 0.f;
    }
    __syncthreads();

    const char* Ah = IS_FFN2 ? (const char*)g_hid_h : (const char*)g_xh;
    const char* Al = IS_FFN2 ? (const char*)g_hid_l : (const char*)g_xl;
    const char* Wh = IS_FFN2 ? (const char*)g_w2h : (const char*)g_w1h;
    const char* Wl = IS_FFN2 ? (const char*)g_w2l : (const char*)g_w1l;

    // ---- cp.async fills ----
    auto fill_stage = [&](int buf, int k0) {
        char* st = smem + buf * STAGE;
        // A: 128 rows x 4 chunks of 16B, hi+lo; 2 passes
        #pragma unroll
        for (int p = 0; p < 2; p++) {
            const int idx = p * 256 + tid;
            const int r = idx >> 2, c = idx & 3;
            const int ent = toks[r];
            const int row = ent >= 0 ? (IS_FFN2 ? ent : (ent >> 1)) : 0;
            const uint32_t sz = ent >= 0 ? 16u : 0u;
            const size_t so = ((size_t)row * KTOT + k0 + c * 8) * 2;
            CPA(sm_u32(st + OFF_AH + r * 80 + c * 16), Ah + so, sz);
            CPA(sm_u32(st + OFF_AL + r * 80 + c * 16), Al + so, sz);
        }
        // B: 32 k-rows x 16 chunks of 16B, hi+lo; 2 passes
        const size_t wbase = ((size_t)e * KTOT + k0) * LDW + n0;
        #pragma unroll
        for (int p = 0; p < 2; p++) {
            const int idx = p * 256 + tid;
            const int k = idx >> 4, c = idx & 15;
            const size_t so = (wbase + (size_t)k * LDW + c * 8) * 2;
            const int doff = k * 256 + ((c ^ (k & 7)) * 16);
            CPB(sm_u32(st + OFF_BH + doff), Wh + so);
            CPB(sm_u32(st + OFF_BL + doff), Wl + so);
        }
    };

    // ---- accumulators ----
    const int wm = wid >> 1, wn = wid & 1;
    float acc[2][8][4];
    #pragma unroll
    for (int mt = 0; mt < 2; mt++)
        #pragma unroll
        for (int nn = 0; nn < 8; nn++)
            #pragma unroll
            for (int i = 0; i < 4; i++) acc[mt][nn][i] = 0.f;

    auto compute_stage = [&](int buf) {
        char* st = smem + buf * STAGE;
        const uint32_t ah = sm_u32(st + OFF_AH);
        const uint32_t al = sm_u32(st + OFF_AL);
        const uint32_t bh = sm_u32(st + OFF_BH);
        const uint32_t bl = sm_u32(st + OFF_BL);
        #pragma unroll
        for (int ks = 0; ks < 2; ks++) {
            // A frags: rows lane&15, k-half lane>>4
            uint32_t a_h[2][4], a_l[2][4];
            #pragma unroll
            for (int mt = 0; mt < 2; mt++) {
                const uint32_t ao = (wm * 32 + mt * 16 + (lane & 15)) * 80
                                  + ks * 32 + (lane >> 4) * 16;
                LDSM_X4(a_h[mt][0], a_h[mt][1], a_h[mt][2], a_h[mt][3], ah + ao);
                LDSM_X4(a_l[mt][0], a_l[mt][1], a_l[mt][2], a_l[mt][3], al + ao);
            }
            // B frags per-bt; term-major interleave over 4 independent chains
            #pragma unroll
            for (int bt = 0; bt < 4; bt++) {
                uint32_t bfh[4], bfl[4];
                const int k = ks * 16 + (lane & 15);
                const int c = ((wn * 64 + bt * 16) >> 3) + (lane >> 4);
                const uint32_t bo = k * 256 + ((c ^ (lane & 7)) * 16);
                LDSM_X4T(bfh[0], bfh[1], bfh[2], bfh[3], bh + bo);
                LDSM_X4T(bfl[0], bfl[1], bfl[2], bfl[3], bl + bo);
                // term 1: Ah*Bh — 4 independent MMAs
                MMA_BF16(acc[0][2 * bt],     a_h[0][0], a_h[0][1], a_h[0][2], a_h[0][3], bfh[0], bfh[1]);
                MMA_BF16(acc[0][2 * bt + 1], a_h[0][0], a_h[0][1], a_h[0][2], a_h[0][3], bfh[2], bfh[3]);
                MMA_BF16(acc[1][2 * bt],     a_h[1][0], a_h[1][1], a_h[1][2], a_h[1][3], bfh[0], bfh[1]);
                MMA_BF16(acc[1][2 * bt + 1], a_h[1][0], a_h[1][1], a_h[1][2], a_h[1][3], bfh[2], bfh[3]);
                // term 2: Ah*Bl
                MMA_BF16(acc[0][2 * bt],     a_h[0][0], a_h[0][1], a_h[0][2], a_h[0][3], bfl[0], bfl[1]);
                MMA_BF16(acc[0][2 * bt + 1], a_h[0][0], a_h[0][1], a_h[0][2], a_h[0][3], bfl[2], bfl[3]);
                MMA_BF16(acc[1][2 * bt],     a_h[1][0], a_h[1][1], a_h[1][2], a_h[1][3], bfl[0], bfl[1]);
                MMA_BF16(acc[1][2 * bt + 1], a_h[1][0], a_h[1][1], a_h[1][2], a_h[1][3], bfl[2], bfl[3]);
                // term 3: Al*Bh
                MMA_BF16(acc[0][2 * bt],     a_l[0][0], a_l[0][1], a_l[0][2], a_l[0][3], bfh[0], bfh[1]);
                MMA_BF16(acc[0][2 * bt + 1], a_l[0][0], a_l[0][1], a_l[0][2], a_l[0][3], bfh[2], bfh[3]);
                MMA_BF16(acc[1][2 * bt],     a_l[1][0], a_l[1][1], a_l[1][2], a_l[1][3], bfh[0], bfh[1]);
                MMA_BF16(acc[1][2 * bt + 1], a_l[1][0], a_l[1][1], a_l[1][2], a_l[1][3], bfh[2], bfh[3]);
            }
        }
    };

    // ---- mainloop: R10 2-stage pipeline ----
    fill_stage(0, 0);
    CP_COMMIT();
    for (int t = 0; t < NT; t++) {
        CP_WAIT0();
        __syncthreads();
        if (t + 1 < NT) {
            fill_stage((t + 1) & 1, (t + 1) * BK);
            CP_COMMIT();
        }
        compute_stage(t & 1);
    }

    // ---- epilogue ----
    const int g  = lane >> 2;
    const int kq = lane & 3;
    const float* be = bias + e * LDW;
    #pragma unroll
    for (int mt = 0; mt < 2; mt++) {
        const int lr0  = wm * 32 + mt * 16 + g;
        const int ent0 = toks[lr0];
        const int ent1 = toks[lr0 + 8];
        #pragma unroll
        for (int nn = 0; nn < 8; nn++) {
            const int c = n0 + wn * 64 + nn * 8 + 2 * kq;
            const float bb0 = be[c], bb1 = be[c + 1];
            if (!IS_FFN2) {
                if (ent0 >= 0) {
                    float v0 = acc[mt][nn][0] + bb0;
                    float v1 = acc[mt][nn][1] + bb1;
                    v0 = 0.5f * v0 * (1.f + erff(v0 * 0.70710678118654752f));
                    v1 = 0.5f * v1 * (1.f + erff(v1 * 0.70710678118654752f));
                    uint32_t h0, l0, h1, l1;
                    bsplit(v0, h0, l0); bsplit(v1, h1, l1);
                    const size_t o = ((size_t)ent0 * HH + c) * 2;
                    *(uint32_t*)((char*)g_hid_h + o) = h0 | (h1 << 16);
                    *(uint32_t*)((char*)g_hid_l + o) = l0 | (l1 << 16);
                }
                if (ent1 >= 0) {
                    float v0 = acc[mt][nn][2] + bb0;
                    float v1 = acc[mt][nn][3] + bb1;
                    v0 = 0.5f * v0 * (1.f + erff(v0 * 0.70710678118654752f));
                    v1 = 0.5f * v1 * (1.f + erff(v1 * 0.70710678118654752f));
                    uint32_t h0, l0, h1, l1;
                    bsplit(v0, h0, l0); bsplit(v1, h1, l1);
                    const size_t o = ((size_t)ent1 * HH + c) * 2;
                    *(uint32_t*)((char*)g_hid_h + o) = h0 | (h1 << 16);
                    *(uint32_t*)((char*)g_hid_l + o) = l0 | (l1 << 16);
                }
            } else {
                if (ent0 >= 0) {
                    const float w = wts[lr0];
                    float* o = outp + (size_t)(ent0 >> 1) * DD + c;
                    atomicAdd(o,     w * (acc[mt][nn][0] + bb0));
                    atomicAdd(o + 1, w * (acc[mt][nn][1] + bb1));
                }
                if (ent1 >= 0) {
                    const float w = wts[lr0 + 8];
                    float* o = outp + (size_t)(ent1 >> 1) * DD + c;
                    atomicAdd(o,     w * (acc[mt][nn][2] + bb0));
                    atomicAdd(o + 1, w * (acc[mt][nn][3] + bb1));
                }
            }
        }
    }
}

// ---------------------------------------------------------------------------
extern "C" void kernel_launch(void* const* d_in, const int* in_sizes, int n_in,
                              void* d_out, int out_size)
{
    const float* x    = (const float*)d_in[0];
    const float* dt   = (const float*)d_in[1];
    const float* dd   = (const float*)d_in[2];
    const float* dr   = (const float*)d_in[3];
    const float* de   = (const float*)d_in[4];
    const float* cemb = (const float*)d_in[5];
    const float* Wg   = (const float*)d_in[6];
    const float* bg   = (const float*)d_in[7];
    const float* Wn   = (const float*)d_in[8];
    const float* bn   = (const float*)d_in[9];
    const float* W1   = (const float*)d_in[10];
    const float* b1   = (const float*)d_in[11];
    const float* W2   = (const float*)d_in[12];
    const float* b2   = (const float*)d_in[13];
    const float* noise= (const float*)d_in[14];
    const int*   city = (const int*)d_in[15];

    float* out   = (float*)d_out;                       // (4096, 512)
    float* gate1 = (float*)d_out + (size_t)NTOK * DD;   // (4096, 10)

    cudaFuncSetAttribute((const void*)moe_mma_kernel<DD, HH, false>,
                         cudaFuncAttributeMaxDynamicSharedMemorySize, SMEM_DYN);
    cudaFuncSetAttribute((const void*)moe_mma_kernel<HH, DD, true>,
                         cudaFuncAttributeMaxDynamicSharedMemorySize, SMEM_DYN);

    cudaMemsetAsync(d_out, 0, (size_t)NTOK * DD * sizeof(float));
    zero_counts_kernel<<<1, 32>>>();

    // pre-split x, W1, W2 to bf16 hi/lo in one launch
    {
        const int nx = NTOK * DD / 4;
        const int nw = EE * DD * HH / 4;
        const int ntot = nx + 2 * nw;
        presplit_all_kernel<<<(ntot + 255) / 256, 256>>>(x, W1, W2);
    }

    router_kernel<<<NTOK / RTOK, 256>>>(x, dt, dd, dr, de, cemb, Wg, bg, Wn, bn,
                                        noise, city, gate1);

    dim3 grid1(HH / BN, NTOK / BM, EE);   // (16, 32, 10)
    moe_mma_kernel<DD, HH, false><<<grid1, 256, SMEM_DYN>>>(b1, nullptr);

    dim3 grid2(DD / BN, NTOK / BM, EE);   // (4, 32, 10)
    moe_mma_kernel<HH, DD, true><<<grid2, 256, SMEM_DYN>>>(b2, out);
}